// round 16
// baseline (speedup 1.0000x reference)
#include <cuda_runtime.h>
#include <cstdint>

#define Bsz 16
#define HW 16384
#define Cdim 128
#define QKVN 384
#define NHEADS 4
#define HDp 32
#define SHIFT 4
#define EPSLN 1e-3f
#define SCALEQ 0.17677669529663689f
#define M_TOTAL (Bsz * HW)
#define NTILES (M_TOTAL / 64)     // 4096
#define GRID_Y 608                // proj persistent grid

// ---- scratch ----
__device__ float g_att[(size_t)M_TOTAL * Cdim];
__device__ float g_pb[(size_t)256 * NHEADS * 4096];

__device__ __forceinline__ int win_row_to_token(int m) {
    int b   = m >> 14;
    int r   = m & 16383;
    int win = r >> 6;
    int n   = r & 63;
    int hb  = win >> 4;
    int wb  = win & 15;
    int h   = ((hb << 3) + (n >> 3) + SHIFT) & 127;
    int w   = ((wb << 3) + (n & 7) + SHIFT) & 127;
    return (b << 14) + (h << 7) + w;
}

// ===================== helpers =====================
__device__ __forceinline__ float to_tf32(float x) {
    float y;
    asm("cvt.rna.tf32.f32 %0, %1;" : "=f"(y) : "f"(x));
    return y;
}
__device__ __forceinline__ uint32_t fbits(float x) { return __float_as_uint(x); }

__device__ __forceinline__ void mma168(float* c, const uint32_t* a, const uint32_t* b) {
    asm volatile(
        "mma.sync.aligned.m16n8k8.row.col.f32.tf32.tf32.f32 "
        "{%0,%1,%2,%3}, {%4,%5,%6,%7}, {%8,%9}, {%0,%1,%2,%3};"
        : "+f"(c[0]), "+f"(c[1]), "+f"(c[2]), "+f"(c[3])
        : "r"(a[0]), "r"(a[1]), "r"(a[2]), "r"(a[3]), "r"(b[0]), "r"(b[1]));
}

__device__ __forceinline__ uint32_t smem_u32(const void* p) {
    uint32_t a;
    asm("{ .reg .u64 t; cvta.to.shared.u64 t, %1; cvt.u32.u64 %0, t; }"
        : "=r"(a) : "l"(p));
    return a;
}
__device__ __forceinline__ void cp16(void* s, const void* g) {
    asm volatile("cp.async.ca.shared.global [%0], [%1], 16;"
                 :: "r"(smem_u32(s)), "l"(g));
}
#define CP_COMMIT() asm volatile("cp.async.commit_group;" ::: "memory")
#define CP_WAIT(n)  asm volatile("cp.async.wait_group %0;" :: "n"(n) : "memory")

// in-block column permutation: w in 0..7 -> 2*(w&3) + (w>>2)
__device__ __forceinline__ int perm8(int w) { return ((w & 3) << 1) | (w >> 2); }

#define PAQ 132
#define PBQ 136
#define PSK 36
#define PSP 68
#define PROJ_SMEM_BYTES ((64 * PAQ + 128 * PBQ) * 4 + 64 * 2 * 8)

// ============================================================
// Kernel PB: combined relpos-bias + mask table.
// ============================================================
__global__ __launch_bounds__(256) void pb_kernel(
    const float* __restrict__ bt, const int* __restrict__ ri,
    const float* __restrict__ mask) {
    const int wimg = blockIdx.x, head = blockIdx.y;
    const float* mrow = mask + (size_t)wimg * 4096;
    float* out = g_pb + ((size_t)(wimg * NHEADS + head)) * 4096;
    for (int i = threadIdx.x; i < 4096; i += 256)
        out[i] = __ldg(&bt[ri[i] * NHEADS + head]) + mrow[i];
}

// ============================================================
// Kernel F: FUSED QKV + attention (R14 config, unchanged).
// ============================================================
#define FQ_A   0
#define FQ_W0  8448
#define FQ_W1  25856
#define FQ_KS  43264
#define FQ_SMEM_FLOATS 52480
#define FQ_SMEM_BYTES (FQ_SMEM_FLOATS * 4)   // 209.9 KB

__global__ __launch_bounds__(256, 1) void fused_qkv_attn_kernel(
    const float* __restrict__ x, const float* __restrict__ wq,
    const float* __restrict__ bq) {
    extern __shared__ float sm[];
    float* As = sm + FQ_A;
    float* W0 = sm + FQ_W0;
    float* W1 = sm + FQ_W1;
    float* Ks = sm + FQ_KS;
    float* Vs = W1;

    const int tid  = threadIdx.x;
    const int w    = tid >> 5;
    const int lane = tid & 31;
    const int gr = lane >> 2, ac = lane & 3;
    const int win    = blockIdx.x;
    const int head   = w & 3;
    const int base_m = (w >> 2) << 5;
    const int base_n = head << 5;

    for (int i = tid; i < 2048; i += 256) {
        int r = i >> 5, c4 = (i & 31) << 2;
        cp16(As + r * PAQ + c4,
             x + (size_t)win_row_to_token((win << 6) + r) * Cdim + c4);
    }
    for (int i = tid; i < 4096; i += 256) {
        int k = i >> 5, n4 = (i & 31) << 2;
        cp16(W0 + k * PBQ + n4, wq + (size_t)k * QKVN + n4);
    }
    CP_COMMIT();
    CP_WAIT(0);
    __syncthreads();

    for (int i = tid; i < 4096; i += 256) {
        int k = i >> 5, n4 = (i & 31) << 2;
        cp16(W1 + k * PBQ + n4, wq + (size_t)k * QKVN + 128 + n4);
    }
    CP_COMMIT();

    float cq[2][4][4];
#pragma unroll
    for (int mt = 0; mt < 2; mt++)
#pragma unroll
        for (int nt = 0; nt < 4; nt++)
#pragma unroll
            for (int j = 0; j < 4; j++) cq[mt][nt][j] = 0.f;

#pragma unroll
    for (int k0 = 0; k0 < 128; k0 += 8) {
        uint32_t a[2][4];
#pragma unroll
        for (int mt = 0; mt < 2; mt++) {
            const float* p = As + (base_m + (mt << 4) + gr) * PAQ + k0 + ac;
            a[mt][0] = fbits(p[0]);
            a[mt][1] = fbits(p[8 * PAQ]);
            a[mt][2] = fbits(p[4]);
            a[mt][3] = fbits(p[8 * PAQ + 4]);
        }
        uint32_t b[4][2];
#pragma unroll
        for (int nt = 0; nt < 4; nt++) {
            const float* p = W0 + (k0 + ac) * PBQ + base_n + gr + (nt << 3);
            b[nt][0] = fbits(p[0]);
            b[nt][1] = fbits(p[4 * PBQ]);
        }
#pragma unroll
        for (int mt = 0; mt < 2; mt++)
#pragma unroll
            for (int nt = 0; nt < 4; nt++)
                mma168(cq[mt][nt], a[mt], b[nt]);
    }
#pragma unroll
    for (int nt = 0; nt < 4; nt++) {
        int col = base_n + (nt << 3) + (ac << 1);
        float bb0 = __ldg(&bq[col]);
        float bb1 = __ldg(&bq[col + 1]);
#pragma unroll
        for (int mt = 0; mt < 2; mt++) {
            cq[mt][nt][0] = (cq[mt][nt][0] + bb0) * SCALEQ;
            cq[mt][nt][1] = (cq[mt][nt][1] + bb1) * SCALEQ;
            cq[mt][nt][2] = (cq[mt][nt][2] + bb0) * SCALEQ;
            cq[mt][nt][3] = (cq[mt][nt][3] + bb1) * SCALEQ;
        }
    }
    __syncthreads();

    for (int i = tid; i < 4096; i += 256) {
        int k = i >> 5, n4 = (i & 31) << 2;
        cp16(W0 + k * PBQ + n4, wq + (size_t)k * QKVN + 256 + n4);
    }
    CP_COMMIT();
    CP_WAIT(1);
    __syncthreads();

    {
        float ck[2][4][4];
#pragma unroll
        for (int mt = 0; mt < 2; mt++)
#pragma unroll
            for (int nt = 0; nt < 4; nt++)
#pragma unroll
                for (int j = 0; j < 4; j++) ck[mt][nt][j] = 0.f;
#pragma unroll
        for (int k0 = 0; k0 < 128; k0 += 8) {
            uint32_t a[2][4];
#pragma unroll
            for (int mt = 0; mt < 2; mt++) {
                const float* p = As + (base_m + (mt << 4) + gr) * PAQ + k0 + ac;
                a[mt][0] = fbits(p[0]);
                a[mt][1] = fbits(p[8 * PAQ]);
                a[mt][2] = fbits(p[4]);
                a[mt][3] = fbits(p[8 * PAQ + 4]);
            }
            uint32_t b[4][2];
#pragma unroll
            for (int nt = 0; nt < 4; nt++) {
                const float* p = W1 + (k0 + ac) * PBQ + base_n + gr + (nt << 3);
                b[nt][0] = fbits(p[0]);
                b[nt][1] = fbits(p[4 * PBQ]);
            }
#pragma unroll
            for (int mt = 0; mt < 2; mt++)
#pragma unroll
                for (int nt = 0; nt < 4; nt++)
                    mma168(ck[mt][nt], a[mt], b[nt]);
        }
        float* kdst = Ks + head * (64 * PSK);
#pragma unroll
        for (int nt = 0; nt < 4; nt++) {
            int lc  = (nt << 3) + (ac << 1);
            int col = 128 + base_n + lc;
            float bb0 = __ldg(&bq[col]);
            float bb1 = __ldg(&bq[col + 1]);
#pragma unroll
            for (int mt = 0; mt < 2; mt++) {
                int row = base_m + (mt << 4) + gr;
                *(float2*)&kdst[row * PSK + lc] =
                    make_float2(ck[mt][nt][0] + bb0, ck[mt][nt][1] + bb1);
                *(float2*)&kdst[(row + 8) * PSK + lc] =
                    make_float2(ck[mt][nt][2] + bb0, ck[mt][nt][3] + bb1);
            }
        }
    }
    CP_WAIT(0);
    __syncthreads();

    float cv[2][4][4];
#pragma unroll
    for (int mt = 0; mt < 2; mt++)
#pragma unroll
        for (int nt = 0; nt < 4; nt++)
#pragma unroll
            for (int j = 0; j < 4; j++) cv[mt][nt][j] = 0.f;
#pragma unroll
    for (int k0 = 0; k0 < 128; k0 += 8) {
        uint32_t a[2][4];
#pragma unroll
        for (int mt = 0; mt < 2; mt++) {
            const float* p = As + (base_m + (mt << 4) + gr) * PAQ + k0 + ac;
            a[mt][0] = fbits(p[0]);
            a[mt][1] = fbits(p[8 * PAQ]);
            a[mt][2] = fbits(p[4]);
            a[mt][3] = fbits(p[8 * PAQ + 4]);
        }
        uint32_t b[4][2];
#pragma unroll
        for (int nt = 0; nt < 4; nt++) {
            const float* p = W0 + (k0 + ac) * PBQ + base_n + gr + (nt << 3);
            b[nt][0] = fbits(p[0]);
            b[nt][1] = fbits(p[4 * PBQ]);
        }
#pragma unroll
        for (int mt = 0; mt < 2; mt++)
#pragma unroll
            for (int nt = 0; nt < 4; nt++)
                mma168(cv[mt][nt], a[mt], b[nt]);
    }
    __syncthreads();

    {
        float* vdst = Vs + head * (64 * PSK);
#pragma unroll
        for (int nt = 0; nt < 4; nt++) {
            int lc  = (nt << 3) + (ac << 1);
            int col = 256 + base_n + lc;
            float bb0 = __ldg(&bq[col]);
            float bb1 = __ldg(&bq[col + 1]);
#pragma unroll
            for (int mt = 0; mt < 2; mt++) {
                int row = base_m + (mt << 4) + gr;
                *(float2*)&vdst[row * PSK + lc] =
                    make_float2(cv[mt][nt][0] + bb0, cv[mt][nt][1] + bb1);
                *(float2*)&vdst[(row + 8) * PSK + lc] =
                    make_float2(cv[mt][nt][2] + bb0, cv[mt][nt][3] + bb1);
            }
        }
    }
    __syncthreads();

    const int wimg = win & 255;
    const float* pbb = g_pb + ((size_t)(wimg * NHEADS + head)) * 4096;
    const float* kp = Ks + head * (64 * PSK);
    const float* vp = Vs + head * (64 * PSK);
    float* qscr = As + w * (16 * PSK);
    float* pp   = W0 + w * (16 * PSP);

    for (int mt = 0; mt < 2; ++mt) {
        const int r0 = base_m + (mt << 4);

        __syncwarp();
#pragma unroll
        for (int nt = 0; nt < 4; nt++) {
            int lc = (nt << 3) + (ac << 1);
            qscr[gr * PSK + lc]           = cq[mt][nt][0];
            qscr[gr * PSK + lc + 1]       = cq[mt][nt][1];
            qscr[(gr + 8) * PSK + lc]     = cq[mt][nt][2];
            qscr[(gr + 8) * PSK + lc + 1] = cq[mt][nt][3];
        }
        __syncwarp();

        float c1[8][4];
#pragma unroll
        for (int nt = 0; nt < 8; nt++)
#pragma unroll
            for (int j = 0; j < 4; j++) c1[nt][j] = 0.f;
#pragma unroll
        for (int k0 = 0; k0 < 32; k0 += 8) {
            uint32_t a[4];
            a[0] = fbits(qscr[gr * PSK + k0 + ac]);
            a[1] = fbits(qscr[(gr + 8) * PSK + k0 + ac]);
            a[2] = fbits(qscr[gr * PSK + k0 + ac + 4]);
            a[3] = fbits(qscr[(gr + 8) * PSK + k0 + ac + 4]);
            uint32_t b[8][2];
#pragma unroll
            for (int nt = 0; nt < 8; nt++) {
                const float* kb = kp + ((nt << 3) + gr) * PSK + k0 + ac;
                b[nt][0] = fbits(kb[0]);
                b[nt][1] = fbits(kb[4]);
            }
#pragma unroll
            for (int nt = 0; nt < 8; nt++) mma168(c1[nt], a, b[nt]);
        }

        float mx0 = -1e30f, mx1 = -1e30f;
#pragma unroll
        for (int nt = 0; nt < 8; nt++) {
            int col = (ac << 1) + (nt << 3);
            float2 p0 = *(const float2*)(pbb + (r0 + gr) * 64 + col);
            float2 p1 = *(const float2*)(pbb + (r0 + gr + 8) * 64 + col);
            c1[nt][0] += p0.x; c1[nt][1] += p0.y;
            c1[nt][2] += p1.x; c1[nt][3] += p1.y;
            mx0 = fmaxf(mx0, fmaxf(c1[nt][0], c1[nt][1]));
            mx1 = fmaxf(mx1, fmaxf(c1[nt][2], c1[nt][3]));
        }
        mx0 = fmaxf(mx0, __shfl_xor_sync(0xffffffffu, mx0, 1));
        mx0 = fmaxf(mx0, __shfl_xor_sync(0xffffffffu, mx0, 2));
        mx1 = fmaxf(mx1, __shfl_xor_sync(0xffffffffu, mx1, 1));
        mx1 = fmaxf(mx1, __shfl_xor_sync(0xffffffffu, mx1, 2));
        float s0 = 0.f, s1 = 0.f;
#pragma unroll
        for (int nt = 0; nt < 8; nt++) {
            c1[nt][0] = __expf(c1[nt][0] - mx0);
            c1[nt][1] = __expf(c1[nt][1] - mx0);
            c1[nt][2] = __expf(c1[nt][2] - mx1);
            c1[nt][3] = __expf(c1[nt][3] - mx1);
            s0 += c1[nt][0] + c1[nt][1];
            s1 += c1[nt][2] + c1[nt][3];
        }
        s0 += __shfl_xor_sync(0xffffffffu, s0, 1);
        s0 += __shfl_xor_sync(0xffffffffu, s0, 2);
        s1 += __shfl_xor_sync(0xffffffffu, s1, 1);
        s1 += __shfl_xor_sync(0xffffffffu, s1, 2);
        float i0 = 1.0f / s0, i1 = 1.0f / s1;

        __syncwarp();
#pragma unroll
        for (int nt = 0; nt < 8; nt++) {
            int col = (ac << 1) + (nt << 3);
            pp[gr * PSP + col]           = to_tf32(c1[nt][0] * i0);
            pp[gr * PSP + col + 1]       = to_tf32(c1[nt][1] * i0);
            pp[(gr + 8) * PSP + col]     = to_tf32(c1[nt][2] * i1);
            pp[(gr + 8) * PSP + col + 1] = to_tf32(c1[nt][3] * i1);
        }
        __syncwarp();

        float co[4][4];
#pragma unroll
        for (int nt = 0; nt < 4; nt++)
#pragma unroll
            for (int j = 0; j < 4; j++) co[nt][j] = 0.f;
#pragma unroll
        for (int k0 = 0; k0 < 64; k0 += 8) {
            uint32_t a[4];
            const float* pa = pp + gr * PSP + k0 + ac;
            a[0] = fbits(pa[0]);
            a[1] = fbits(pa[8 * PSP]);
            a[2] = fbits(pa[4]);
            a[3] = fbits(pa[8 * PSP + 4]);
            uint32_t b[4][2];
#pragma unroll
            for (int nt = 0; nt < 4; nt++) {
                const float* vb = vp + (k0 + ac) * PSK + (nt << 3) + gr;
                b[nt][0] = fbits(vb[0]);
                b[nt][1] = fbits(vb[4 * PSK]);
            }
#pragma unroll
            for (int nt = 0; nt < 4; nt++) mma168(co[nt], a, b[nt]);
        }

        float* ob0 = g_att + ((size_t)((win << 6) + r0 + gr)) * Cdim + base_n;
        float* ob1 = g_att + ((size_t)((win << 6) + r0 + gr + 8)) * Cdim + base_n;
#pragma unroll
        for (int nt = 0; nt < 4; nt++) {
            int col = (ac << 1) + (nt << 3);
            *(float2*)(ob0 + col) = make_float2(co[nt][0], co[nt][1]);
            *(float2*)(ob1 + col) = make_float2(co[nt][2], co[nt][3]);
        }
        __syncwarp();
    }
}

// ============================================================
// Kernel C: proj GEMM (R12 config, unchanged).
// ============================================================
__global__ __launch_bounds__(256, 2) void proj_mma_kernel(
    const float* __restrict__ x, const float* __restrict__ wp_g,
    const float* __restrict__ bp, const float* __restrict__ g1,
    const float* __restrict__ be1, float* __restrict__ out) {
    extern __shared__ float sm[];
    float* As = sm;
    float* Bs = As + 64 * PAQ;
    float2* pbuf = (float2*)(Bs + 128 * PBQ);

    const int tid  = threadIdx.x;
    const int w    = tid >> 5;
    const int lane = tid & 31;

    const int base_m = (w >> 1) << 4;
    const int base_n = (w & 1) << 6;
    const int half   = w & 1;
    const int gr = lane >> 2, ac = lane & 3;
    const int bn = base_n + gr;

    for (int i = tid; i < 4096; i += 256) {
        int k = i >> 5, n4 = (i & 31) << 2;
        cp16(Bs + k * PBQ + n4, wp_g + (size_t)k * Cdim + n4);
    }
    {
        int mb = blockIdx.x << 6;
        for (int i = tid; i < 2048; i += 256) {
            int r = i >> 5, c4 = (i & 31) << 2;
            cp16(As + r * PAQ + c4, g_att + (((size_t)(mb + r)) << 7) + c4);
        }
    }
    CP_COMMIT();

    for (int mt = blockIdx.x; mt < NTILES; mt += GRID_Y) {
        CP_WAIT(0);
        __syncthreads();
        const int mbase = mt << 6;

        float c2[8][4];
#pragma unroll
        for (int nt = 0; nt < 8; nt++)
#pragma unroll
            for (int j = 0; j < 4; j++) c2[nt][j] = 0.f;

#pragma unroll
        for (int k0 = 0; k0 < 128; k0 += 8) {
            uint32_t a[4];
            {
                const float* p = As + (base_m + gr) * PAQ + k0 + ac;
                a[0] = fbits(p[0]);
                a[1] = fbits(p[8 * PAQ]);
                a[2] = fbits(p[4]);
                a[3] = fbits(p[8 * PAQ + 4]);
            }
            uint32_t b[8][2];
#pragma unroll
            for (int nt = 0; nt < 8; nt++) {
                const float* p = Bs + (k0 + ac) * PBQ + bn + (nt << 3);
                b[nt][0] = fbits(p[0]);
                b[nt][1] = fbits(p[4 * PBQ]);
            }
#pragma unroll
            for (int nt = 0; nt < 8; nt++) mma168(c2[nt], a, b[nt]);
        }
        __syncthreads();

        if (mt + GRID_Y < NTILES) {
            int mb = (mt + GRID_Y) << 6;
            for (int i = tid; i < 2048; i += 256) {
                int r = i >> 5, c4 = (i & 31) << 2;
                cp16(As + r * PAQ + c4, g_att + (((size_t)(mb + r)) << 7) + c4);
            }
            CP_COMMIT();
        }

        float s1a = 0.f, s2a = 0.f, s1b = 0.f, s2b = 0.f;
#pragma unroll
        for (int nt = 0; nt < 8; nt++) {
            int col = base_n + (nt << 3) + (ac << 1);
            float bb0 = __ldg(&bp[col]);
            float bb1 = __ldg(&bp[col + 1]);
            c2[nt][0] += bb0; c2[nt][1] += bb1;
            c2[nt][2] += bb0; c2[nt][3] += bb1;
            s1a += c2[nt][0] + c2[nt][1];
            s2a += c2[nt][0] * c2[nt][0] + c2[nt][1] * c2[nt][1];
            s1b += c2[nt][2] + c2[nt][3];
            s2b += c2[nt][2] * c2[nt][2] + c2[nt][3] * c2[nt][3];
        }
        s1a += __shfl_xor_sync(0xffffffffu, s1a, 1);
        s1a += __shfl_xor_sync(0xffffffffu, s1a, 2);
        s2a += __shfl_xor_sync(0xffffffffu, s2a, 1);
        s2a += __shfl_xor_sync(0xffffffffu, s2a, 2);
        s1b += __shfl_xor_sync(0xffffffffu, s1b, 1);
        s1b += __shfl_xor_sync(0xffffffffu, s1b, 2);
        s2b += __shfl_xor_sync(0xffffffffu, s2b, 1);
        s2b += __shfl_xor_sync(0xffffffffu, s2b, 2);
        if (ac == 0) {
            pbuf[(base_m + gr) * 2 + half]     = make_float2(s1a, s2a);
            pbuf[(base_m + gr + 8) * 2 + half] = make_float2(s1b, s2b);
        }
        __syncthreads();
        {
            float2 oa = pbuf[(base_m + gr) * 2 + (half ^ 1)];
            float2 ob = pbuf[(base_m + gr + 8) * 2 + (half ^ 1)];
            s1a += oa.x; s2a += oa.y;
            s1b += ob.x; s2b += ob.y;
        }
        float meanA = s1a * (1.0f / 128.0f);
        float rsA   = rsqrtf(s2a * (1.0f / 128.0f) - meanA * meanA + EPSLN);
        float meanB = s1b * (1.0f / 128.0f);
        float rsB   = rsqrtf(s2b * (1.0f / 128.0f) - meanB * meanB + EPSLN);

        size_t offA = ((size_t)win_row_to_token(mbase + base_m + gr)) << 7;
        size_t offB = ((size_t)win_row_to_token(mbase + base_m + gr + 8)) << 7;
#pragma unroll
        for (int nt = 0; nt < 8; nt++) {
            int col = base_n + (nt << 3) + (ac << 1);
            float gg0 = __ldg(&g1[col]),  gg1 = __ldg(&g1[col + 1]);
            float ee0 = __ldg(&be1[col]), ee1 = __ldg(&be1[col + 1]);
            float2 xa = *(const float2*)(x + offA + col);
            float2 xb = *(const float2*)(x + offB + col);
            float2 oA, oB;
            oA.x = xa.x + (c2[nt][0] - meanA) * rsA * gg0 + ee0;
            oA.y = xa.y + (c2[nt][1] - meanA) * rsA * gg1 + ee1;
            oB.x = xb.x + (c2[nt][2] - meanB) * rsB * gg0 + ee0;
            oB.y = xb.y + (c2[nt][3] - meanB) * rsB * gg1 + ee1;
            *(float2*)(out + offA + col) = oA;
            *(float2*)(out + offB + col) = oB;
        }
    }
}

// ============================================================
// Kernel D: tf32 warp-MMA MLP, slab 64, PERMUTED A/Hs layouts
// (fragment pairs adjacent -> LDS.64). W1 double-buffered,
// W2 single staggered. M=128, 256 thr, 1 CTA/SM, ~210 KB.
// ============================================================
#define PA   136
#define PW1  72
#define PH2  72
#define PW2B 136
#define MLP_A_F   (128 * PA)      // 17408
#define MLP_W1_F  (128 * PW1)     // 9216 per buf
#define MLP_H_F   (128 * PH2)     // 9216
#define MLP_W2_F  (64 * PW2B)     // 8704 (single)
#define MLP_SMEM_FLOATS (MLP_A_F + 2 * MLP_W1_F + MLP_H_F + MLP_W2_F)
#define MLP_SMEM_BYTES  (MLP_SMEM_FLOATS * 4)   // 215040 B

__global__ __launch_bounds__(256, 1) void mlp_mma_kernel(
    const float* __restrict__ w1g, const float* __restrict__ b1,
    const float* __restrict__ w2g, const float* __restrict__ b2,
    const float* __restrict__ g2v, const float* __restrict__ be2v,
    float* __restrict__ io) {
    extern __shared__ float sm[];
    float* As  = sm;                      // [128][PA] permuted cols
    float* W1b = As + MLP_A_F;            // [2][128][PW1] k-major
    float* Hs  = W1b + 2 * MLP_W1_F;      // [128][PH2] permuted cols
    float* W2s = Hs + MLP_H_F;            // [64][PW2B] k-major

    const int tid  = threadIdx.x;
    const int w    = tid >> 5;
    const int lane = tid & 31;
    const int mbase = blockIdx.x << 7;

    const int base_m  = (w >> 1) << 5;    // 0,32,64,96
    const int base_n1 = (w & 1) << 5;     // fc1: 0 or 32
    const int base_n2 = (w & 1) << 6;     // fc2: 0 or 64

    const int gr = lane >> 2, ac = lane & 3;

    // ---- weights slab 0 via cp.async (overlaps the A staging below) ----
    for (int i = tid; i < 2048; i += 256) {
        int k = i >> 4, n4 = (i & 15) << 2;
        cp16(W1b + k * PW1 + n4, w1g + (size_t)k * 512 + n4);
    }
    for (int i = tid; i < 2048; i += 256) {
        int k = i >> 5, n4 = (i & 31) << 2;
        cp16(W2s + k * PW2B + n4, w2g + ((size_t)k << 7) + n4);
    }
    CP_COMMIT();

    // ---- A tile: load + column-permute into As ----
    // warp covers 8 rows x 16 cols per iteration
#pragma unroll
    for (int it = 0; it < 16; ++it) {
        int chunk = it * 8 + w;                 // 0..127
        int r  = ((chunk & 15) << 3) + (lane >> 2);
        int c4 = ((chunk >> 4) << 4) + ((lane & 3) << 2);
        float4 v = *(const float4*)(io + (((size_t)(mbase + r)) << 7) + c4);
        int base = r * PA + (c4 & ~7);
        int off  = (c4 >> 2) & 1;
        As[base + 0 + off] = v.x;
        As[base + 2 + off] = v.y;
        As[base + 4 + off] = v.z;
        As[base + 6 + off] = v.w;
    }

    float c2[2][8][4];
#pragma unroll
    for (int mt = 0; mt < 2; mt++)
#pragma unroll
        for (int nt = 0; nt < 8; nt++)
#pragma unroll
            for (int j = 0; j < 4; j++) c2[mt][nt][j] = 0.f;

    for (int c = 0; c < 8; ++c) {
        if (c + 1 < 8) {
            float* w1d = W1b + ((c + 1) & 1) * MLP_W1_F;
            for (int i = tid; i < 2048; i += 256) {
                int k = i >> 4, n4 = (i & 15) << 2;
                cp16(w1d + k * PW1 + n4,
                     w1g + (size_t)k * 512 + ((c + 1) << 6) + n4);
            }
            CP_COMMIT();
            CP_WAIT(1);   // W1(c)+W2(c) resident
        } else {
            CP_WAIT(0);
        }
        __syncthreads();

        const float* w1s = W1b + (c & 1) * MLP_W1_F;

        // ---- fc1: warp 32x32, k=128, A via LDS.64 pairs ----
        float c1[2][4][4];
#pragma unroll
        for (int mt = 0; mt < 2; mt++)
#pragma unroll
            for (int nt = 0; nt < 4; nt++)
#pragma unroll
                for (int j = 0; j < 4; j++) c1[mt][nt][j] = 0.f;

        const int bn1 = base_n1 + gr;
#pragma unroll
        for (int k0 = 0; k0 < 128; k0 += 8) {
            uint32_t a[2][4];
#pragma unroll
            for (int mt = 0; mt < 2; mt++) {
                int r1 = base_m + (mt << 4) + gr;
                float2 lo = *(const float2*)&As[r1 * PA + k0 + (ac << 1)];
                float2 hi = *(const float2*)&As[(r1 + 8) * PA + k0 + (ac << 1)];
                a[mt][0] = fbits(lo.x);
                a[mt][1] = fbits(hi.x);
                a[mt][2] = fbits(lo.y);
                a[mt][3] = fbits(hi.y);
            }
            uint32_t b[4][2];
#pragma unroll
            for (int nt = 0; nt < 4; nt++) {
                const float* p = w1s + (k0 + ac) * PW1 + bn1 + (nt << 3);
                b[nt][0] = fbits(p[0]);
                b[nt][1] = fbits(p[4 * PW1]);
            }
#pragma unroll
            for (int mt = 0; mt < 2; mt++)
#pragma unroll
                for (int nt = 0; nt < 4; nt++)
                    mma168(c1[mt][nt], a[mt], b[nt]);
        }

        // bias + exact GELU -> Hs (permuted columns)
#pragma unroll
        for (int mt = 0; mt < 2; mt++) {
            int r0 = base_m + (mt << 4) + gr;
#pragma unroll
            for (int nt = 0; nt < 4; nt++) {
                int blk = base_n1 + (nt << 3);
                int w8  = ac << 1;
                int col = blk + w8;
                float bb0 = __ldg(&b1[(c << 6) + col]);
                float bb1 = __ldg(&b1[(c << 6) + col + 1]);
                int p0 = perm8(w8), p1 = perm8(w8 + 1);
#pragma unroll
                for (int half = 0; half < 2; half++) {
                    int r = r0 + half * 8;
                    float v0 = c1[mt][nt][half * 2 + 0] + bb0;
                    float v1 = c1[mt][nt][half * 2 + 1] + bb1;
                    v0 = 0.5f * v0 * (1.0f + erff(v0 * 0.70710678118654752f));
                    v1 = 0.5f * v1 * (1.0f + erff(v1 * 0.70710678118654752f));
                    Hs[r * PH2 + blk + p0] = v0;
                    Hs[r * PH2 + blk + p1] = v1;
                }
            }
        }
        __syncthreads();   // Hs visible

        // ---- fc2: warp 32x64, k=64 slab, Hs via LDS.64 pairs ----
        const int bn2 = base_n2 + gr;
#pragma unroll
        for (int k0 = 0; k0 < 64; k0 += 8) {
            uint32_t a[2][4];
#pragma unroll
            for (int mt = 0; mt < 2; mt++) {
                int r1 = base_m + (mt << 4) + gr;
                float2 lo = *(const float2*)&Hs[r1 * PH2 + k0 + (ac << 1)];
                float2 hi = *(const float2*)&Hs[(r1 + 8) * PH2 + k0 + (ac << 1)];
                a[mt][0] = fbits(lo.x);
                a[mt][1] = fbits(hi.x);
                a[mt][2] = fbits(lo.y);
                a[mt][3] = fbits(hi.y);
            }
            uint32_t b[8][2];
#pragma unroll
            for (int nt = 0; nt < 8; nt++) {
                const float* p = W2s + (k0 + ac) * PW2B + bn2 + (nt << 3);
                b[nt][0] = fbits(p[0]);
                b[nt][1] = fbits(p[4 * PW2B]);
            }
#pragma unroll
            for (int mt = 0; mt < 2; mt++)
#pragma unroll
                for (int nt = 0; nt < 8; nt++)
                    mma168(c2[mt][nt], a[mt], b[nt]);
        }
        __syncthreads();   // all warps done reading W2(c) / Hs

        if (c + 1 < 8) {
            for (int i = tid; i < 2048; i += 256) {
                int k = i >> 5, n4 = (i & 31) << 2;
                cp16(W2s + k * PW2B + n4,
                     w2g + ((size_t)(((c + 1) << 6) + k) << 7) + n4);
            }
            CP_COMMIT();
        }
    }

    // ---- epilogue: +b2 -> ob (reuse W1b region, plain layout), LN, residual ----
    float* ob = W1b;   // 2*9216 = 18432 >= 128*PA = 17408
#pragma unroll
    for (int mt = 0; mt < 2; mt++) {
        int r0 = base_m + (mt << 4) + gr;
#pragma unroll
        for (int nt = 0; nt < 8; nt++) {
            int col = base_n2 + (nt << 3) + (ac << 1);
            float bb0 = __ldg(&b2[col]);
            float bb1 = __ldg(&b2[col + 1]);
#pragma unroll
            for (int half = 0; half < 2; half++) {
                int r = r0 + half * 8;
                ob[r * PA + col]     = c2[mt][nt][half * 2 + 0] + bb0;
                ob[r * PA + col + 1] = c2[mt][nt][half * 2 + 1] + bb1;
            }
        }
    }
    __syncthreads();

    {
        int r   = tid >> 1;
        int h64 = (tid & 1) << 6;
        float s1 = 0.f, s2 = 0.f;
#pragma unroll
        for (int j = 0; j < 64; j += 4) {
            float4 v = *(float4*)&ob[r * PA + h64 + j];
            s1 += v.x + v.y + v.z + v.w;
            s2 += v.x * v.x + v.y * v.y + v.z * v.z + v.w * v.w;
        }
        s1 += __shfl_xor_sync(0xffffffffu, s1, 1);
        s2 += __shfl_xor_sync(0xffffffffu, s2, 1);
        float mean = s1 * (1.0f / 128.0f);
        float var  = s2 * (1.0f / 128.0f) - mean * mean;
        float rs   = rsqrtf(var + EPSLN);
        size_t rowoff = ((size_t)(mbase + r)) << 7;
#pragma unroll
        for (int j = 0; j < 64; j += 4) {
            int cc = h64 + j;
            float4 v  = *(float4*)&ob[r * PA + cc];
            float4 xr = *(const float4*)(io + rowoff + cc);
            float4 gg = *(const float4*)(g2v + cc);
            float4 bb = *(const float4*)(be2v + cc);
            float4 o;
            o.x = xr.x + (v.x - mean) * rs * gg.x + bb.x;
            o.y = xr.y + (v.y - mean) * rs * gg.y + bb.y;
            o.z = xr.z + (v.z - mean) * rs * gg.z + bb.z;
            o.w = xr.w + (v.w - mean) * rs * gg.w + bb.w;
            *(float4*)(io + rowoff + cc) = o;
        }
    }
}

// ============================================================
extern "C" void kernel_launch(void* const* d_in, const int* in_sizes, int n_in,
                              void* d_out, int out_size) {
    const float* x          = (const float*)d_in[0];
    const float* w_qkv      = (const float*)d_in[1];
    const float* b_qkv      = (const float*)d_in[2];
    const float* bias_table = (const float*)d_in[3];
    const float* w_proj     = (const float*)d_in[4];
    const float* b_proj     = (const float*)d_in[5];
    const float* g1         = (const float*)d_in[6];
    const float* be1        = (const float*)d_in[7];
    const float* w_fc1      = (const float*)d_in[8];
    const float* b_fc1      = (const float*)d_in[9];
    const float* w_fc2      = (const float*)d_in[10];
    const float* b_fc2      = (const float*)d_in[11];
    const float* g2         = (const float*)d_in[12];
    const float* be2        = (const float*)d_in[13];
    const int*   rel_index  = (const int*)d_in[14];
    const float* attn_mask  = (const float*)d_in[15];
    float* out = (float*)d_out;

    cudaFuncSetAttribute(fused_qkv_attn_kernel,
                         cudaFuncAttributeMaxDynamicSharedMemorySize, FQ_SMEM_BYTES);
    cudaFuncSetAttribute(proj_mma_kernel, cudaFuncAttributeMaxDynamicSharedMemorySize,
                         PROJ_SMEM_BYTES);
    cudaFuncSetAttribute(mlp_mma_kernel, cudaFuncAttributeMaxDynamicSharedMemorySize,
                         MLP_SMEM_BYTES);

    pb_kernel<<<dim3(256, NHEADS), 256>>>(bias_table, rel_index, attn_mask);
    fused_qkv_attn_kernel<<<4096, 256, FQ_SMEM_BYTES>>>(x, w_qkv, b_qkv);
    proj_mma_kernel<<<GRID_Y, 256, PROJ_SMEM_BYTES>>>(x, w_proj, b_proj, g1, be1, out);
    mlp_mma_kernel<<<M_TOTAL / 128, 256, MLP_SMEM_BYTES>>>(
        w_fc1, b_fc1, w_fc2, b_fc2, g2, be2, out);
}

// round 17
// speedup vs baseline: 1.0098x; 1.0098x over previous
#include <cuda_runtime.h>
#include <cstdint>

#define Bsz 16
#define HW 16384
#define Cdim 128
#define QKVN 384
#define NHEADS 4
#define HDp 32
#define SHIFT 4
#define EPSLN 1e-3f
#define SCALEQ 0.17677669529663689f
#define M_TOTAL (Bsz * HW)
#define NTILES (M_TOTAL / 64)     // 4096
#define GRID_Y 608                // proj persistent grid

// ---- scratch ----
__device__ float g_att[(size_t)M_TOTAL * Cdim];
__device__ float g_pb[(size_t)256 * NHEADS * 4096];

__device__ __forceinline__ int win_row_to_token(int m) {
    int b   = m >> 14;
    int r   = m & 16383;
    int win = r >> 6;
    int n   = r & 63;
    int hb  = win >> 4;
    int wb  = win & 15;
    int h   = ((hb << 3) + (n >> 3) + SHIFT) & 127;
    int w   = ((wb << 3) + (n & 7) + SHIFT) & 127;
    return (b << 14) + (h << 7) + w;
}

// ===================== helpers =====================
__device__ __forceinline__ float to_tf32(float x) {
    float y;
    asm("cvt.rna.tf32.f32 %0, %1;" : "=f"(y) : "f"(x));
    return y;
}
__device__ __forceinline__ uint32_t fbits(float x) { return __float_as_uint(x); }

__device__ __forceinline__ void mma168(float* c, const uint32_t* a, const uint32_t* b) {
    asm volatile(
        "mma.sync.aligned.m16n8k8.row.col.f32.tf32.tf32.f32 "
        "{%0,%1,%2,%3}, {%4,%5,%6,%7}, {%8,%9}, {%0,%1,%2,%3};"
        : "+f"(c[0]), "+f"(c[1]), "+f"(c[2]), "+f"(c[3])
        : "r"(a[0]), "r"(a[1]), "r"(a[2]), "r"(a[3]), "r"(b[0]), "r"(b[1]));
}

__device__ __forceinline__ uint32_t smem_u32(const void* p) {
    uint32_t a;
    asm("{ .reg .u64 t; cvta.to.shared.u64 t, %1; cvt.u32.u64 %0, t; }"
        : "=r"(a) : "l"(p));
    return a;
}
__device__ __forceinline__ void cp16(void* s, const void* g) {
    asm volatile("cp.async.ca.shared.global [%0], [%1], 16;"
                 :: "r"(smem_u32(s)), "l"(g));
}
#define CP_COMMIT() asm volatile("cp.async.commit_group;" ::: "memory")
#define CP_WAIT(n)  asm volatile("cp.async.wait_group %0;" :: "n"(n) : "memory")
#define BAR_SYNC(id, cnt) asm volatile("bar.sync %0, %1;" :: "r"(id), "r"(cnt) : "memory")

#define PAQ 132
#define PBQ 136
#define PSK 36
#define PSP 68
#define PROJ_SMEM_BYTES ((64 * PAQ + 128 * PBQ) * 4 + 64 * 2 * 8)

// ============================================================
// Kernel PB: combined relpos-bias + mask table.
// ============================================================
__global__ __launch_bounds__(256) void pb_kernel(
    const float* __restrict__ bt, const int* __restrict__ ri,
    const float* __restrict__ mask) {
    const int wimg = blockIdx.x, head = blockIdx.y;
    const float* mrow = mask + (size_t)wimg * 4096;
    float* out = g_pb + ((size_t)(wimg * NHEADS + head)) * 4096;
    for (int i = threadIdx.x; i < 4096; i += 256)
        out[i] = __ldg(&bt[ri[i] * NHEADS + head]) + mrow[i];
}

// ============================================================
// Kernel F: FUSED QKV + attention (R14 config, unchanged).
// ============================================================
#define FQ_A   0
#define FQ_W0  8448
#define FQ_W1  25856
#define FQ_KS  43264
#define FQ_SMEM_FLOATS 52480
#define FQ_SMEM_BYTES (FQ_SMEM_FLOATS * 4)   // 209.9 KB

__global__ __launch_bounds__(256, 1) void fused_qkv_attn_kernel(
    const float* __restrict__ x, const float* __restrict__ wq,
    const float* __restrict__ bq) {
    extern __shared__ float sm[];
    float* As = sm + FQ_A;
    float* W0 = sm + FQ_W0;
    float* W1 = sm + FQ_W1;
    float* Ks = sm + FQ_KS;
    float* Vs = W1;

    const int tid  = threadIdx.x;
    const int w    = tid >> 5;
    const int lane = tid & 31;
    const int gr = lane >> 2, ac = lane & 3;
    const int win    = blockIdx.x;
    const int head   = w & 3;
    const int base_m = (w >> 2) << 5;
    const int base_n = head << 5;

    for (int i = tid; i < 2048; i += 256) {
        int r = i >> 5, c4 = (i & 31) << 2;
        cp16(As + r * PAQ + c4,
             x + (size_t)win_row_to_token((win << 6) + r) * Cdim + c4);
    }
    for (int i = tid; i < 4096; i += 256) {
        int k = i >> 5, n4 = (i & 31) << 2;
        cp16(W0 + k * PBQ + n4, wq + (size_t)k * QKVN + n4);
    }
    CP_COMMIT();
    CP_WAIT(0);
    __syncthreads();

    for (int i = tid; i < 4096; i += 256) {
        int k = i >> 5, n4 = (i & 31) << 2;
        cp16(W1 + k * PBQ + n4, wq + (size_t)k * QKVN + 128 + n4);
    }
    CP_COMMIT();

    float cq[2][4][4];
#pragma unroll
    for (int mt = 0; mt < 2; mt++)
#pragma unroll
        for (int nt = 0; nt < 4; nt++)
#pragma unroll
            for (int j = 0; j < 4; j++) cq[mt][nt][j] = 0.f;

#pragma unroll
    for (int k0 = 0; k0 < 128; k0 += 8) {
        uint32_t a[2][4];
#pragma unroll
        for (int mt = 0; mt < 2; mt++) {
            const float* p = As + (base_m + (mt << 4) + gr) * PAQ + k0 + ac;
            a[mt][0] = fbits(p[0]);
            a[mt][1] = fbits(p[8 * PAQ]);
            a[mt][2] = fbits(p[4]);
            a[mt][3] = fbits(p[8 * PAQ + 4]);
        }
        uint32_t b[4][2];
#pragma unroll
        for (int nt = 0; nt < 4; nt++) {
            const float* p = W0 + (k0 + ac) * PBQ + base_n + gr + (nt << 3);
            b[nt][0] = fbits(p[0]);
            b[nt][1] = fbits(p[4 * PBQ]);
        }
#pragma unroll
        for (int mt = 0; mt < 2; mt++)
#pragma unroll
            for (int nt = 0; nt < 4; nt++)
                mma168(cq[mt][nt], a[mt], b[nt]);
    }
#pragma unroll
    for (int nt = 0; nt < 4; nt++) {
        int col = base_n + (nt << 3) + (ac << 1);
        float bb0 = __ldg(&bq[col]);
        float bb1 = __ldg(&bq[col + 1]);
#pragma unroll
        for (int mt = 0; mt < 2; mt++) {
            cq[mt][nt][0] = (cq[mt][nt][0] + bb0) * SCALEQ;
            cq[mt][nt][1] = (cq[mt][nt][1] + bb1) * SCALEQ;
            cq[mt][nt][2] = (cq[mt][nt][2] + bb0) * SCALEQ;
            cq[mt][nt][3] = (cq[mt][nt][3] + bb1) * SCALEQ;
        }
    }
    __syncthreads();

    for (int i = tid; i < 4096; i += 256) {
        int k = i >> 5, n4 = (i & 31) << 2;
        cp16(W0 + k * PBQ + n4, wq + (size_t)k * QKVN + 256 + n4);
    }
    CP_COMMIT();
    CP_WAIT(1);
    __syncthreads();

    {
        float ck[2][4][4];
#pragma unroll
        for (int mt = 0; mt < 2; mt++)
#pragma unroll
            for (int nt = 0; nt < 4; nt++)
#pragma unroll
                for (int j = 0; j < 4; j++) ck[mt][nt][j] = 0.f;
#pragma unroll
        for (int k0 = 0; k0 < 128; k0 += 8) {
            uint32_t a[2][4];
#pragma unroll
            for (int mt = 0; mt < 2; mt++) {
                const float* p = As + (base_m + (mt << 4) + gr) * PAQ + k0 + ac;
                a[mt][0] = fbits(p[0]);
                a[mt][1] = fbits(p[8 * PAQ]);
                a[mt][2] = fbits(p[4]);
                a[mt][3] = fbits(p[8 * PAQ + 4]);
            }
            uint32_t b[4][2];
#pragma unroll
            for (int nt = 0; nt < 4; nt++) {
                const float* p = W1 + (k0 + ac) * PBQ + base_n + gr + (nt << 3);
                b[nt][0] = fbits(p[0]);
                b[nt][1] = fbits(p[4 * PBQ]);
            }
#pragma unroll
            for (int mt = 0; mt < 2; mt++)
#pragma unroll
                for (int nt = 0; nt < 4; nt++)
                    mma168(ck[mt][nt], a[mt], b[nt]);
        }
        float* kdst = Ks + head * (64 * PSK);
#pragma unroll
        for (int nt = 0; nt < 4; nt++) {
            int lc  = (nt << 3) + (ac << 1);
            int col = 128 + base_n + lc;
            float bb0 = __ldg(&bq[col]);
            float bb1 = __ldg(&bq[col + 1]);
#pragma unroll
            for (int mt = 0; mt < 2; mt++) {
                int row = base_m + (mt << 4) + gr;
                *(float2*)&kdst[row * PSK + lc] =
                    make_float2(ck[mt][nt][0] + bb0, ck[mt][nt][1] + bb1);
                *(float2*)&kdst[(row + 8) * PSK + lc] =
                    make_float2(ck[mt][nt][2] + bb0, ck[mt][nt][3] + bb1);
            }
        }
    }
    CP_WAIT(0);
    __syncthreads();

    float cv[2][4][4];
#pragma unroll
    for (int mt = 0; mt < 2; mt++)
#pragma unroll
        for (int nt = 0; nt < 4; nt++)
#pragma unroll
            for (int j = 0; j < 4; j++) cv[mt][nt][j] = 0.f;
#pragma unroll
    for (int k0 = 0; k0 < 128; k0 += 8) {
        uint32_t a[2][4];
#pragma unroll
        for (int mt = 0; mt < 2; mt++) {
            const float* p = As + (base_m + (mt << 4) + gr) * PAQ + k0 + ac;
            a[mt][0] = fbits(p[0]);
            a[mt][1] = fbits(p[8 * PAQ]);
            a[mt][2] = fbits(p[4]);
            a[mt][3] = fbits(p[8 * PAQ + 4]);
        }
        uint32_t b[4][2];
#pragma unroll
        for (int nt = 0; nt < 4; nt++) {
            const float* p = W0 + (k0 + ac) * PBQ + base_n + gr + (nt << 3);
            b[nt][0] = fbits(p[0]);
            b[nt][1] = fbits(p[4 * PBQ]);
        }
#pragma unroll
        for (int mt = 0; mt < 2; mt++)
#pragma unroll
            for (int nt = 0; nt < 4; nt++)
                mma168(cv[mt][nt], a[mt], b[nt]);
    }
    __syncthreads();

    {
        float* vdst = Vs + head * (64 * PSK);
#pragma unroll
        for (int nt = 0; nt < 4; nt++) {
            int lc  = (nt << 3) + (ac << 1);
            int col = 256 + base_n + lc;
            float bb0 = __ldg(&bq[col]);
            float bb1 = __ldg(&bq[col + 1]);
#pragma unroll
            for (int mt = 0; mt < 2; mt++) {
                int row = base_m + (mt << 4) + gr;
                *(float2*)&vdst[row * PSK + lc] =
                    make_float2(cv[mt][nt][0] + bb0, cv[mt][nt][1] + bb1);
                *(float2*)&vdst[(row + 8) * PSK + lc] =
                    make_float2(cv[mt][nt][2] + bb0, cv[mt][nt][3] + bb1);
            }
        }
    }
    __syncthreads();

    const int wimg = win & 255;
    const float* pbb = g_pb + ((size_t)(wimg * NHEADS + head)) * 4096;
    const float* kp = Ks + head * (64 * PSK);
    const float* vp = Vs + head * (64 * PSK);
    float* qscr = As + w * (16 * PSK);
    float* pp   = W0 + w * (16 * PSP);

    for (int mt = 0; mt < 2; ++mt) {
        const int r0 = base_m + (mt << 4);

        __syncwarp();
#pragma unroll
        for (int nt = 0; nt < 4; nt++) {
            int lc = (nt << 3) + (ac << 1);
            qscr[gr * PSK + lc]           = cq[mt][nt][0];
            qscr[gr * PSK + lc + 1]       = cq[mt][nt][1];
            qscr[(gr + 8) * PSK + lc]     = cq[mt][nt][2];
            qscr[(gr + 8) * PSK + lc + 1] = cq[mt][nt][3];
        }
        __syncwarp();

        float c1[8][4];
#pragma unroll
        for (int nt = 0; nt < 8; nt++)
#pragma unroll
            for (int j = 0; j < 4; j++) c1[nt][j] = 0.f;
#pragma unroll
        for (int k0 = 0; k0 < 32; k0 += 8) {
            uint32_t a[4];
            a[0] = fbits(qscr[gr * PSK + k0 + ac]);
            a[1] = fbits(qscr[(gr + 8) * PSK + k0 + ac]);
            a[2] = fbits(qscr[gr * PSK + k0 + ac + 4]);
            a[3] = fbits(qscr[(gr + 8) * PSK + k0 + ac + 4]);
            uint32_t b[8][2];
#pragma unroll
            for (int nt = 0; nt < 8; nt++) {
                const float* kb = kp + ((nt << 3) + gr) * PSK + k0 + ac;
                b[nt][0] = fbits(kb[0]);
                b[nt][1] = fbits(kb[4]);
            }
#pragma unroll
            for (int nt = 0; nt < 8; nt++) mma168(c1[nt], a, b[nt]);
        }

        float mx0 = -1e30f, mx1 = -1e30f;
#pragma unroll
        for (int nt = 0; nt < 8; nt++) {
            int col = (ac << 1) + (nt << 3);
            float2 p0 = *(const float2*)(pbb + (r0 + gr) * 64 + col);
            float2 p1 = *(const float2*)(pbb + (r0 + gr + 8) * 64 + col);
            c1[nt][0] += p0.x; c1[nt][1] += p0.y;
            c1[nt][2] += p1.x; c1[nt][3] += p1.y;
            mx0 = fmaxf(mx0, fmaxf(c1[nt][0], c1[nt][1]));
            mx1 = fmaxf(mx1, fmaxf(c1[nt][2], c1[nt][3]));
        }
        mx0 = fmaxf(mx0, __shfl_xor_sync(0xffffffffu, mx0, 1));
        mx0 = fmaxf(mx0, __shfl_xor_sync(0xffffffffu, mx0, 2));
        mx1 = fmaxf(mx1, __shfl_xor_sync(0xffffffffu, mx1, 1));
        mx1 = fmaxf(mx1, __shfl_xor_sync(0xffffffffu, mx1, 2));
        float s0 = 0.f, s1 = 0.f;
#pragma unroll
        for (int nt = 0; nt < 8; nt++) {
            c1[nt][0] = __expf(c1[nt][0] - mx0);
            c1[nt][1] = __expf(c1[nt][1] - mx0);
            c1[nt][2] = __expf(c1[nt][2] - mx1);
            c1[nt][3] = __expf(c1[nt][3] - mx1);
            s0 += c1[nt][0] + c1[nt][1];
            s1 += c1[nt][2] + c1[nt][3];
        }
        s0 += __shfl_xor_sync(0xffffffffu, s0, 1);
        s0 += __shfl_xor_sync(0xffffffffu, s0, 2);
        s1 += __shfl_xor_sync(0xffffffffu, s1, 1);
        s1 += __shfl_xor_sync(0xffffffffu, s1, 2);
        float i0 = 1.0f / s0, i1 = 1.0f / s1;

        __syncwarp();
#pragma unroll
        for (int nt = 0; nt < 8; nt++) {
            int col = (ac << 1) + (nt << 3);
            pp[gr * PSP + col]           = to_tf32(c1[nt][0] * i0);
            pp[gr * PSP + col + 1]       = to_tf32(c1[nt][1] * i0);
            pp[(gr + 8) * PSP + col]     = to_tf32(c1[nt][2] * i1);
            pp[(gr + 8) * PSP + col + 1] = to_tf32(c1[nt][3] * i1);
        }
        __syncwarp();

        float co[4][4];
#pragma unroll
        for (int nt = 0; nt < 4; nt++)
#pragma unroll
            for (int j = 0; j < 4; j++) co[nt][j] = 0.f;
#pragma unroll
        for (int k0 = 0; k0 < 64; k0 += 8) {
            uint32_t a[4];
            const float* pa = pp + gr * PSP + k0 + ac;
            a[0] = fbits(pa[0]);
            a[1] = fbits(pa[8 * PSP]);
            a[2] = fbits(pa[4]);
            a[3] = fbits(pa[8 * PSP + 4]);
            uint32_t b[4][2];
#pragma unroll
            for (int nt = 0; nt < 4; nt++) {
                const float* vb = vp + (k0 + ac) * PSK + (nt << 3) + gr;
                b[nt][0] = fbits(vb[0]);
                b[nt][1] = fbits(vb[4 * PSK]);
            }
#pragma unroll
            for (int nt = 0; nt < 4; nt++) mma168(co[nt], a, b[nt]);
        }

        float* ob0 = g_att + ((size_t)((win << 6) + r0 + gr)) * Cdim + base_n;
        float* ob1 = g_att + ((size_t)((win << 6) + r0 + gr + 8)) * Cdim + base_n;
#pragma unroll
        for (int nt = 0; nt < 4; nt++) {
            int col = (ac << 1) + (nt << 3);
            *(float2*)(ob0 + col) = make_float2(co[nt][0], co[nt][1]);
            *(float2*)(ob1 + col) = make_float2(co[nt][2], co[nt][3]);
        }
        __syncwarp();
    }
}

// ============================================================
// Kernel C: proj GEMM (R12 config, unchanged).
// ============================================================
__global__ __launch_bounds__(256, 2) void proj_mma_kernel(
    const float* __restrict__ x, const float* __restrict__ wp_g,
    const float* __restrict__ bp, const float* __restrict__ g1,
    const float* __restrict__ be1, float* __restrict__ out) {
    extern __shared__ float sm[];
    float* As = sm;
    float* Bs = As + 64 * PAQ;
    float2* pbuf = (float2*)(Bs + 128 * PBQ);

    const int tid  = threadIdx.x;
    const int w    = tid >> 5;
    const int lane = tid & 31;

    const int base_m = (w >> 1) << 4;
    const int base_n = (w & 1) << 6;
    const int half   = w & 1;
    const int gr = lane >> 2, ac = lane & 3;
    const int bn = base_n + gr;

    for (int i = tid; i < 4096; i += 256) {
        int k = i >> 5, n4 = (i & 31) << 2;
        cp16(Bs + k * PBQ + n4, wp_g + (size_t)k * Cdim + n4);
    }
    {
        int mb = blockIdx.x << 6;
        for (int i = tid; i < 2048; i += 256) {
            int r = i >> 5, c4 = (i & 31) << 2;
            cp16(As + r * PAQ + c4, g_att + (((size_t)(mb + r)) << 7) + c4);
        }
    }
    CP_COMMIT();

    for (int mt = blockIdx.x; mt < NTILES; mt += GRID_Y) {
        CP_WAIT(0);
        __syncthreads();
        const int mbase = mt << 6;

        float c2[8][4];
#pragma unroll
        for (int nt = 0; nt < 8; nt++)
#pragma unroll
            for (int j = 0; j < 4; j++) c2[nt][j] = 0.f;

#pragma unroll
        for (int k0 = 0; k0 < 128; k0 += 8) {
            uint32_t a[4];
            {
                const float* p = As + (base_m + gr) * PAQ + k0 + ac;
                a[0] = fbits(p[0]);
                a[1] = fbits(p[8 * PAQ]);
                a[2] = fbits(p[4]);
                a[3] = fbits(p[8 * PAQ + 4]);
            }
            uint32_t b[8][2];
#pragma unroll
            for (int nt = 0; nt < 8; nt++) {
                const float* p = Bs + (k0 + ac) * PBQ + bn + (nt << 3);
                b[nt][0] = fbits(p[0]);
                b[nt][1] = fbits(p[4 * PBQ]);
            }
#pragma unroll
            for (int nt = 0; nt < 8; nt++) mma168(c2[nt], a, b[nt]);
        }
        __syncthreads();

        if (mt + GRID_Y < NTILES) {
            int mb = (mt + GRID_Y) << 6;
            for (int i = tid; i < 2048; i += 256) {
                int r = i >> 5, c4 = (i & 31) << 2;
                cp16(As + r * PAQ + c4, g_att + (((size_t)(mb + r)) << 7) + c4);
            }
            CP_COMMIT();
        }

        float s1a = 0.f, s2a = 0.f, s1b = 0.f, s2b = 0.f;
#pragma unroll
        for (int nt = 0; nt < 8; nt++) {
            int col = base_n + (nt << 3) + (ac << 1);
            float bb0 = __ldg(&bp[col]);
            float bb1 = __ldg(&bp[col + 1]);
            c2[nt][0] += bb0; c2[nt][1] += bb1;
            c2[nt][2] += bb0; c2[nt][3] += bb1;
            s1a += c2[nt][0] + c2[nt][1];
            s2a += c2[nt][0] * c2[nt][0] + c2[nt][1] * c2[nt][1];
            s1b += c2[nt][2] + c2[nt][3];
            s2b += c2[nt][2] * c2[nt][2] + c2[nt][3] * c2[nt][3];
        }
        s1a += __shfl_xor_sync(0xffffffffu, s1a, 1);
        s1a += __shfl_xor_sync(0xffffffffu, s1a, 2);
        s2a += __shfl_xor_sync(0xffffffffu, s2a, 1);
        s2a += __shfl_xor_sync(0xffffffffu, s2a, 2);
        s1b += __shfl_xor_sync(0xffffffffu, s1b, 1);
        s1b += __shfl_xor_sync(0xffffffffu, s1b, 2);
        s2b += __shfl_xor_sync(0xffffffffu, s2b, 1);
        s2b += __shfl_xor_sync(0xffffffffu, s2b, 2);
        if (ac == 0) {
            pbuf[(base_m + gr) * 2 + half]     = make_float2(s1a, s2a);
            pbuf[(base_m + gr + 8) * 2 + half] = make_float2(s1b, s2b);
        }
        __syncthreads();
        {
            float2 oa = pbuf[(base_m + gr) * 2 + (half ^ 1)];
            float2 ob = pbuf[(base_m + gr + 8) * 2 + (half ^ 1)];
            s1a += oa.x; s2a += oa.y;
            s1b += ob.x; s2b += ob.y;
        }
        float meanA = s1a * (1.0f / 128.0f);
        float rsA   = rsqrtf(s2a * (1.0f / 128.0f) - meanA * meanA + EPSLN);
        float meanB = s1b * (1.0f / 128.0f);
        float rsB   = rsqrtf(s2b * (1.0f / 128.0f) - meanB * meanB + EPSLN);

        size_t offA = ((size_t)win_row_to_token(mbase + base_m + gr)) << 7;
        size_t offB = ((size_t)win_row_to_token(mbase + base_m + gr + 8)) << 7;
#pragma unroll
        for (int nt = 0; nt < 8; nt++) {
            int col = base_n + (nt << 3) + (ac << 1);
            float gg0 = __ldg(&g1[col]),  gg1 = __ldg(&g1[col + 1]);
            float ee0 = __ldg(&be1[col]), ee1 = __ldg(&be1[col + 1]);
            float2 xa = *(const float2*)(x + offA + col);
            float2 xb = *(const float2*)(x + offB + col);
            float2 oA, oB;
            oA.x = xa.x + (c2[nt][0] - meanA) * rsA * gg0 + ee0;
            oA.y = xa.y + (c2[nt][1] - meanA) * rsA * gg1 + ee1;
            oB.x = xb.x + (c2[nt][2] - meanB) * rsB * gg0 + ee0;
            oB.y = xb.y + (c2[nt][3] - meanB) * rsB * gg1 + ee1;
            *(float2*)(out + offA + col) = oA;
            *(float2*)(out + offB + col) = oB;
        }
    }
}

// ============================================================
// Kernel D: tf32 warp-MMA MLP, slab 64 (R15 config) with the
// post-GELU CTA sync replaced by a per-pair named barrier.
// W1 double-buffered, W2 single staggered. 1 CTA/SM, ~206 KB.
// ============================================================
#define PA   132
#define PW1  72
#define PH2  68
#define PW2B 136
#define MLP_A_F   (128 * PA)      // 16896
#define MLP_W1_F  (128 * PW1)     // 9216 per buf
#define MLP_H_F   (128 * PH2)     // 8704
#define MLP_W2_F  (64 * PW2B)     // 8704 (single)
#define MLP_SMEM_FLOATS (MLP_A_F + 2 * MLP_W1_F + MLP_H_F + MLP_W2_F)
#define MLP_SMEM_BYTES  (MLP_SMEM_FLOATS * 4)   // 210944 B

__global__ __launch_bounds__(256, 1) void mlp_mma_kernel(
    const float* __restrict__ w1g, const float* __restrict__ b1,
    const float* __restrict__ w2g, const float* __restrict__ b2,
    const float* __restrict__ g2v, const float* __restrict__ be2v,
    float* __restrict__ io) {
    extern __shared__ float sm[];
    float* As  = sm;
    float* W1b = As + MLP_A_F;            // [2][128][PW1]
    float* Hs  = W1b + 2 * MLP_W1_F;      // [128][PH2]
    float* W2s = Hs + MLP_H_F;            // [64][PW2B]

    const int tid  = threadIdx.x;
    const int w    = tid >> 5;
    const int lane = tid & 31;
    const int mbase = blockIdx.x << 7;

    const int base_m  = (w >> 1) << 5;    // 0,32,64,96
    const int base_n1 = (w & 1) << 5;     // fc1: 0 or 32
    const int base_n2 = (w & 1) << 6;     // fc2: 0 or 64
    const int pair_bar = 1 + (w >> 1);    // named barrier per warp pair

    const int gr = lane >> 2, ac = lane & 3;

    // ---- G0: A + W1(0) + W2(0) ----
    for (int i = tid; i < 4096; i += 256) {
        int r = i >> 5, c4 = (i & 31) << 2;
        cp16(As + r * PA + c4, io + (((size_t)(mbase + r)) << 7) + c4);
    }
    for (int i = tid; i < 2048; i += 256) {
        int k = i >> 4, n4 = (i & 15) << 2;
        cp16(W1b + k * PW1 + n4, w1g + (size_t)k * 512 + n4);
    }
    for (int i = tid; i < 2048; i += 256) {
        int k = i >> 5, n4 = (i & 31) << 2;
        cp16(W2s + k * PW2B + n4, w2g + ((size_t)k << 7) + n4);
    }
    CP_COMMIT();

    float c2[2][8][4];
#pragma unroll
    for (int mt = 0; mt < 2; mt++)
#pragma unroll
        for (int nt = 0; nt < 8; nt++)
#pragma unroll
            for (int j = 0; j < 4; j++) c2[mt][nt][j] = 0.f;

    for (int c = 0; c < 8; ++c) {
        if (c + 1 < 8) {
            float* w1d = W1b + ((c + 1) & 1) * MLP_W1_F;
            for (int i = tid; i < 2048; i += 256) {
                int k = i >> 4, n4 = (i & 15) << 2;
                cp16(w1d + k * PW1 + n4,
                     w1g + (size_t)k * 512 + ((c + 1) << 6) + n4);
            }
            CP_COMMIT();
            CP_WAIT(1);   // W1(c)+W2(c) resident
        } else {
            CP_WAIT(0);
        }
        __syncthreads();

        const float* w1s = W1b + (c & 1) * MLP_W1_F;

        // ---- fc1: warp 32x32, k=128 ----
        float c1[2][4][4];
#pragma unroll
        for (int mt = 0; mt < 2; mt++)
#pragma unroll
            for (int nt = 0; nt < 4; nt++)
#pragma unroll
                for (int j = 0; j < 4; j++) c1[mt][nt][j] = 0.f;

        const int bn1 = base_n1 + gr;
#pragma unroll
        for (int k0 = 0; k0 < 128; k0 += 8) {
            uint32_t a[2][4];
#pragma unroll
            for (int mt = 0; mt < 2; mt++) {
                const float* p = As + (base_m + (mt << 4) + gr) * PA + k0 + ac;
                a[mt][0] = fbits(p[0]);
                a[mt][1] = fbits(p[8 * PA]);
                a[mt][2] = fbits(p[4]);
                a[mt][3] = fbits(p[8 * PA + 4]);
            }
            uint32_t b[4][2];
#pragma unroll
            for (int nt = 0; nt < 4; nt++) {
                const float* p = w1s + (k0 + ac) * PW1 + bn1 + (nt << 3);
                b[nt][0] = fbits(p[0]);
                b[nt][1] = fbits(p[4 * PW1]);
            }
#pragma unroll
            for (int mt = 0; mt < 2; mt++)
#pragma unroll
                for (int nt = 0; nt < 4; nt++)
                    mma168(c1[mt][nt], a[mt], b[nt]);
        }

        // bias + exact GELU -> Hs
#pragma unroll
        for (int mt = 0; mt < 2; mt++) {
            int r0 = base_m + (mt << 4) + gr;
#pragma unroll
            for (int nt = 0; nt < 4; nt++) {
                int col = base_n1 + (nt << 3) + (ac << 1);
                float bb0 = __ldg(&b1[(c << 6) + col]);
                float bb1 = __ldg(&b1[(c << 6) + col + 1]);
#pragma unroll
                for (int half = 0; half < 2; half++) {
                    int r = r0 + half * 8;
                    float v0 = c1[mt][nt][half * 2 + 0] + bb0;
                    float v1 = c1[mt][nt][half * 2 + 1] + bb1;
                    v0 = 0.5f * v0 * (1.0f + erff(v0 * 0.70710678118654752f));
                    v1 = 0.5f * v1 * (1.0f + erff(v1 * 0.70710678118654752f));
                    Hs[r * PH2 + col]     = v0;
                    Hs[r * PH2 + col + 1] = v1;
                }
            }
        }
        // fc2 only reads Hs rows written by this warp's pair -> pair barrier
        BAR_SYNC(pair_bar, 64);

        // ---- fc2: warp 32x64, k=64 slab ----
        const int bn2 = base_n2 + gr;
#pragma unroll
        for (int k0 = 0; k0 < 64; k0 += 8) {
            uint32_t a[2][4];
#pragma unroll
            for (int mt = 0; mt < 2; mt++) {
                const float* p = Hs + (base_m + (mt << 4) + gr) * PH2 + k0 + ac;
                a[mt][0] = fbits(p[0]);
                a[mt][1] = fbits(p[8 * PH2]);
                a[mt][2] = fbits(p[4]);
                a[mt][3] = fbits(p[8 * PH2 + 4]);
            }
            uint32_t b[8][2];
#pragma unroll
            for (int nt = 0; nt < 8; nt++) {
                const float* p = W2s + (k0 + ac) * PW2B + bn2 + (nt << 3);
                b[nt][0] = fbits(p[0]);
                b[nt][1] = fbits(p[4 * PW2B]);
            }
#pragma unroll
            for (int mt = 0; mt < 2; mt++)
#pragma unroll
                for (int nt = 0; nt < 8; nt++)
                    mma168(c2[mt][nt], a[mt], b[nt]);
        }
        __syncthreads();   // all warps done reading W2(c) / Hs before overwrite

        if (c + 1 < 8) {
            for (int i = tid; i < 2048; i += 256) {
                int k = i >> 5, n4 = (i & 31) << 2;
                cp16(W2s + k * PW2B + n4,
                     w2g + ((size_t)(((c + 1) << 6) + k) << 7) + n4);
            }
            CP_COMMIT();
        }
    }

    // ---- epilogue: +b2 -> ob (reuse W1b region), LN, residual ----
    float* ob = W1b;   // 2*9216 = 18432 >= 16896
#pragma unroll
    for (int mt = 0; mt < 2; mt++) {
        int r0 = base_m + (mt << 4) + gr;
#pragma unroll
        for (int nt = 0; nt < 8; nt++) {
            int col = base_n2 + (nt << 3) + (ac << 1);
            float bb0 = __ldg(&b2[col]);
            float bb1 = __ldg(&b2[col + 1]);
#pragma unroll
            for (int half = 0; half < 2; half++) {
                int r = r0 + half * 8;
                ob[r * PA + col]     = c2[mt][nt][half * 2 + 0] + bb0;
                ob[r * PA + col + 1] = c2[mt][nt][half * 2 + 1] + bb1;
            }
        }
    }
    __syncthreads();

    {
        int r   = tid >> 1;
        int h64 = (tid & 1) << 6;
        float s1 = 0.f, s2 = 0.f;
#pragma unroll
        for (int j = 0; j < 64; j += 4) {
            float4 v = *(float4*)&ob[r * PA + h64 + j];
            s1 += v.x + v.y + v.z + v.w;
            s2 += v.x * v.x + v.y * v.y + v.z * v.z + v.w * v.w;
        }
        s1 += __shfl_xor_sync(0xffffffffu, s1, 1);
        s2 += __shfl_xor_sync(0xffffffffu, s2, 1);
        float mean = s1 * (1.0f / 128.0f);
        float var  = s2 * (1.0f / 128.0f) - mean * mean;
        float rs   = rsqrtf(var + EPSLN);
        size_t rowoff = ((size_t)(mbase + r)) << 7;
#pragma unroll
        for (int j = 0; j < 64; j += 4) {
            int cc = h64 + j;
            float4 v  = *(float4*)&ob[r * PA + cc];
            float4 xr = *(const float4*)(io + rowoff + cc);
            float4 gg = *(const float4*)(g2v + cc);
            float4 bb = *(const float4*)(be2v + cc);
            float4 o;
            o.x = xr.x + (v.x - mean) * rs * gg.x + bb.x;
            o.y = xr.y + (v.y - mean) * rs * gg.y + bb.y;
            o.z = xr.z + (v.z - mean) * rs * gg.z + bb.z;
            o.w = xr.w + (v.w - mean) * rs * gg.w + bb.w;
            *(float4*)(io + rowoff + cc) = o;
        }
    }
}

// ============================================================
extern "C" void kernel_launch(void* const* d_in, const int* in_sizes, int n_in,
                              void* d_out, int out_size) {
    const float* x          = (const float*)d_in[0];
    const float* w_qkv      = (const float*)d_in[1];
    const float* b_qkv      = (const float*)d_in[2];
    const float* bias_table = (const float*)d_in[3];
    const float* w_proj     = (const float*)d_in[4];
    const float* b_proj     = (const float*)d_in[5];
    const float* g1         = (const float*)d_in[6];
    const float* be1        = (const float*)d_in[7];
    const float* w_fc1      = (const float*)d_in[8];
    const float* b_fc1      = (const float*)d_in[9];
    const float* w_fc2      = (const float*)d_in[10];
    const float* b_fc2      = (const float*)d_in[11];
    const float* g2         = (const float*)d_in[12];
    const float* be2        = (const float*)d_in[13];
    const int*   rel_index  = (const int*)d_in[14];
    const float* attn_mask  = (const float*)d_in[15];
    float* out = (float*)d_out;

    cudaFuncSetAttribute(fused_qkv_attn_kernel,
                         cudaFuncAttributeMaxDynamicSharedMemorySize, FQ_SMEM_BYTES);
    cudaFuncSetAttribute(proj_mma_kernel, cudaFuncAttributeMaxDynamicSharedMemorySize,
                         PROJ_SMEM_BYTES);
    cudaFuncSetAttribute(mlp_mma_kernel, cudaFuncAttributeMaxDynamicSharedMemorySize,
                         MLP_SMEM_BYTES);

    pb_kernel<<<dim3(256, NHEADS), 256>>>(bias_table, rel_index, attn_mask);
    fused_qkv_attn_kernel<<<4096, 256, FQ_SMEM_BYTES>>>(x, w_qkv, b_qkv);
    proj_mma_kernel<<<GRID_Y, 256, PROJ_SMEM_BYTES>>>(x, w_proj, b_proj, g1, be1, out);
    mlp_mma_kernel<<<M_TOTAL / 128, 256, MLP_SMEM_BYTES>>>(
        w_fc1, b_fc1, w_fc2, b_fc2, g2, be2, out);
}